// round 17
// baseline (speedup 1.0000x reference)
#include <cuda_runtime.h>
#include <math_constants.h>
#include <cstdint>

#define NN    10000   // nodes
#define D     128     // feature dim
#define TOPK  8
#define DEG   32
#define OUTCH 128
#define INCH  9       // K+1
#define KS    9       // kernel size
#define XOUT  120     // D - K
#define HALF  60      // XOUT/2 : outputs paired (x, x+HALF)
#define NPAIR 68      // interleaved window length: 60 + KS - 1

// Duplicated weight pairs (w,w), layout [c][o][10] (pair 9 = pad):
// 80B per o, 16B-aligned -> 5x LDG.128 per (c,o). Table 92KB, L1-hot.
__device__ __align__(16) float2 g_wdup[INCH][OUTCH][10];

__global__ void prep_weights_kernel(const float* __restrict__ cw)
{
    int idx = blockIdx.x * blockDim.x + threadIdx.x;
    if (idx >= INCH * OUTCH * 10) return;
    int t = idx % 10;
    int o = (idx / 10) % OUTCH;
    int c = idx / (10 * OUTCH);
    float w = (t < KS) ? cw[(size_t)o * (INCH * KS) + c * KS + t] : 0.0f;
    g_wdup[c][o][t] = make_float2(w, w);
}

__device__ __forceinline__ unsigned long long ffma2(unsigned long long a,
                                                    unsigned long long b,
                                                    unsigned long long c)
{
    unsigned long long d;
    asm("fma.rn.f32x2 %0, %1, %2, %3;" : "=l"(d) : "l"(a), "l"(b), "l"(c));
    return d;
}

__global__ __launch_bounds__(128, 6)
void lgcl_fused_kernel(const float* __restrict__ nf,
                       const int*   __restrict__ adj,
                       const float* __restrict__ cb,
                       float*       __restrict__ out)
{
    // interleaved sel: selp[c][i] = (col_i, col_{i+60}), i = 0..67
    __shared__ __align__(16) float2 selp[INCH][NPAIR];
    __shared__ int nbrs[DEG];
    __shared__ int cnt;

    const int n   = blockIdx.x;
    const int tid = threadIdx.x;     // 128 threads

    if (tid == 0) cnt = 0;
    if (tid < DEG) nbrs[tid] = 0;
    __syncthreads();

    // ---- Phase A: scan adjacency row (MLP 4), compact neighbor indices ----
    {
        const int4* row4 = reinterpret_cast<const int4*>(adj + (size_t)n * NN);
        #pragma unroll
        for (int it = 0; it < 5; it++) {
            int4 v[4];
            int  ii[4];
            #pragma unroll
            for (int q = 0; q < 4; q++) {
                int i = tid + it * 512 + q * 128;
                ii[q] = i;
                v[q] = (i < NN / 4) ? row4[i] : make_int4(0, 0, 0, 0);
            }
            #pragma unroll
            for (int q = 0; q < 4; q++) {
                int4 w = v[q];
                if (w.x | w.y | w.z | w.w) {
                    int e = 4 * ii[q];
                    if (w.x) nbrs[atomicAdd(&cnt, 1)] = e + 0;
                    if (w.y) nbrs[atomicAdd(&cnt, 1)] = e + 1;
                    if (w.z) nbrs[atomicAdd(&cnt, 1)] = e + 2;
                    if (w.w) nbrs[atomicAdd(&cnt, 1)] = e + 3;
                }
            }
        }
    }
    __syncthreads();
    const int m = cnt;   // number of real neighbors (<= 32)

    // ---- Phase B: per-column top-8, write interleaved pairs directly ----
    {
        const int d = tid;           // column index, 0..127
        float v[DEG];
        #pragma unroll
        for (int j = 0; j < DEG; j++)
            v[j] = (j < m) ? nf[(size_t)nbrs[j] * D + d] : -CUDART_INF_F;

        float tk[TOPK];
        #pragma unroll
        for (int s = 0; s < TOPK; s++) tk[s] = -CUDART_INF_F;

        #pragma unroll
        for (int j = 0; j < DEG; j++) {
            float x = v[j];
            #pragma unroll
            for (int s = 0; s < TOPK; s++) {
                float hi = fmaxf(tk[s], x);
                x        = fminf(tk[s], x);
                tk[s]    = hi;
            }
        }
        // torch zero-pads missing neighbors before topk: insert (8-m) zeros
        for (int z = m; z < TOPK; z++) {
            float x = 0.0f;
            #pragma unroll
            for (int s = 0; s < TOPK; s++) {
                float hi = fmaxf(tk[s], x);
                x        = fminf(tk[s], x);
                tk[s]    = hi;
            }
        }

        float colv[INCH];
        colv[0] = nf[(size_t)n * D + d];      // self feature
        #pragma unroll
        for (int s = 0; s < TOPK; s++) colv[1 + s] = tk[s];

        if (d < NPAIR) {
            #pragma unroll
            for (int c = 0; c < INCH; c++) selp[c][d].x = colv[c];
        }
        if (d >= HALF) {
            #pragma unroll
            for (int c = 0; c < INCH; c++) selp[c][d - HALF].y = colv[c];
        }
    }
    __syncthreads();

    // ---- Phase C: Conv1d, far-pair packed f32x2, 128-bit operand loads ----
    // acc pair p computes (out[p], out[p+60]):
    //   acc[p] += selp[c][p+t] * (w_{c,t}, w_{c,t})
    {
        const int o = tid;           // output channel
        const float bias = cb[o];
        float* op = out + ((size_t)n * OUTCH + o) * XOUT;

        for (int pb = 0; pb < HALF; pb += 12) {         // 5 chunks of 12 pairs
            unsigned long long acc[12];
            #pragma unroll
            for (int u = 0; u < 12; u++) acc[u] = 0ull;

            for (int c = 0; c < INCH; c++) {
                // weights: 5 x LDG.128 (pairs 0..9, pair 9 is pad)
                unsigned long long W[KS];
                {
                    const ulonglong2* Wp =
                        reinterpret_cast<const ulonglong2*>(&g_wdup[c][o][0]);
                    ulonglong2 w01 = Wp[0];
                    ulonglong2 w23 = Wp[1];
                    ulonglong2 w45 = Wp[2];
                    ulonglong2 w67 = Wp[3];
                    ulonglong2 w89 = Wp[4];
                    W[0] = w01.x; W[1] = w01.y;
                    W[2] = w23.x; W[3] = w23.y;
                    W[4] = w45.x; W[5] = w45.y;
                    W[6] = w67.x; W[7] = w67.y;
                    W[8] = w89.x;               // w89.y = pad, unused
                }

                // window pairs pb..pb+19 via 10 x LDS.128 (pb even -> aligned)
                const ulonglong2* S2 =
                    reinterpret_cast<const ulonglong2*>(&selp[c][pb]);
                unsigned long long P[20];
                #pragma unroll
                for (int i = 0; i < 7; i++) {
                    ulonglong2 q = S2[i];
                    P[2 * i] = q.x; P[2 * i + 1] = q.y;
                }
                #pragma unroll
                for (int p = 0; p < 6; p++) {
                    #pragma unroll
                    for (int t = 0; t < KS; t++)
                        acc[p] = ffma2(P[p + t], W[t], acc[p]);
                }
                #pragma unroll
                for (int i = 7; i < 10; i++) {
                    ulonglong2 q = S2[i];
                    P[2 * i] = q.x; P[2 * i + 1] = q.y;
                }
                #pragma unroll
                for (int p = 6; p < 12; p++) {
                    #pragma unroll
                    for (int t = 0; t < KS; t++)
                        acc[p] = ffma2(P[p + t], W[t], acc[p]);
                }
            }

            // split pairs: x-halves -> op[pb..pb+11], y-halves -> op[pb+60..]
            float lo[12], hi[12];
            #pragma unroll
            for (int u = 0; u < 12; u++) {
                float2 a = *reinterpret_cast<float2*>(&acc[u]);
                lo[u] = a.x + bias;
                hi[u] = a.y + bias;
            }
            #pragma unroll
            for (int u = 0; u < 12; u += 4) {
                *reinterpret_cast<float4*>(op + pb + u) =
                    make_float4(lo[u], lo[u + 1], lo[u + 2], lo[u + 3]);
                *reinterpret_cast<float4*>(op + pb + HALF + u) =
                    make_float4(hi[u], hi[u + 1], hi[u + 2], hi[u + 3]);
            }
        }
    }
}

extern "C" void kernel_launch(void* const* d_in, const int* in_sizes, int n_in,
                              void* d_out, int out_size)
{
    const float* nf  = (const float*)d_in[0];   // [10000, 128]
    const int*   adj = (const int*)  d_in[1];   // [10000, 10000]
    const float* cw  = (const float*)d_in[2];   // [128, 9, 9]
    const float* cb  = (const float*)d_in[3];   // [128]
    float*       out = (float*)d_out;           // [10000, 128, 120]

    prep_weights_kernel<<<(INCH * OUTCH * 10 + 127) / 128, 128>>>(cw);
    lgcl_fused_kernel<<<NN, 128>>>(nf, adj, cb, out);
}